// round 6
// baseline (speedup 1.0000x reference)
#include <cuda_runtime.h>
#include <cuda_bf16.h>

// LateralLayer: B=4, C_IN=C_OUT=64, H=W=128, K=5 (LOC=2)
// d_out (float32): [0:N) x_lateral | [N:2N) xn | [2N:3N) x_lateral_bin
// N = 4*64*128*128 = 4194304.

#define BB   4
#define CC   64
#define HH   128
#define WW   128
#define KK   5
#define CKK  (CC * KK * KK)   // 1600
#define HWSZ (HH * WW)        // 16384
#define NSL  (BB * CC)        // 256
#define NEL  (NSL * HWSZ)     // 4194304
#define NTHR 512
#define NV   (HWSZ / 4 / NTHR)   // 8 float4 vectors per thread

// Scratch (device globals; allocation is forbidden)
__device__ float g_s[BB * HWSZ];      // channel-sum per pixel
__device__ float g_invm[BB * HWSZ];   // 1 / max(boxsum, K)

// ---------------------------------------------------------------------------
// Kernel 1: channel sum  s[b,h,w] = sum_i x[b,i,h,w]   (float4 vectorized)
// 128 thr x 128 blocks; x stays L2-resident for the lateral kernel.
// ---------------------------------------------------------------------------
__global__ void chansum_kernel(const float* __restrict__ x) {
    int v = blockIdx.x * blockDim.x + threadIdx.x;    // vector index (4 px)
    if (v >= (BB * HWSZ) / 4) return;
    int p  = v << 2;
    int b  = p >> 14;
    int hw = p & (HWSZ - 1);
    const float4* xb = (const float4*)(x + ((long)b * CC * HWSZ));
    int vo = hw >> 2;
    float4 s = make_float4(0.f, 0.f, 0.f, 0.f);
#pragma unroll
    for (int i = 0; i < CC; i++) {
        float4 t = __ldg(&xb[(i << 12) + vo]);       // 4096 float4 per channel
        s.x += t.x; s.y += t.y; s.z += t.z; s.w += t.w;
    }
    ((float4*)g_s)[v] = s;
}

// ---------------------------------------------------------------------------
// Kernel 2: 5x5 box sum (zero pad) of g_s, invm = 1/max(sum, 5)  (256KB total)
// ---------------------------------------------------------------------------
__global__ void box_kernel() {
    int p = blockIdx.x * blockDim.x + threadIdx.x;
    if (p >= BB * HWSZ) return;
    int b  = p >> 14;
    int hw = p & (HWSZ - 1);
    int h = hw >> 7, w = hw & (WW - 1);
    const float* sb = g_s + (b << 14);
    float acc = 0.f;
#pragma unroll
    for (int dy = -2; dy <= 2; dy++) {
        int hy = h + dy;
        if ((unsigned)hy >= (unsigned)HH) continue;
#pragma unroll
        for (int dx = -2; dx <= 2; dx++) {
            int wx = w + dx;
            if ((unsigned)wx >= (unsigned)WW) continue;
            acc += sb[(hy << 7) + wx];
        }
    }
    g_invm[p] = 1.f / fmaxf(acc, (float)KK);
}

// ---------------------------------------------------------------------------
// Kernel 3 (fused): sparse lateral conv + normalization + max + binarize.
// One block per (b,o) slice; 512 thr x occupancy 2 -> all 256 blocks fit in
// ONE wave (296 slots on 148 SMs). Conv results register-cached (8 float4),
// so pass 2 is stores-only (streaming stores: outputs are never re-read).
// Weight row compacted deterministically (warp-ordered ballot) -> correct
// for any W; identity init degenerates to 1 tap.
// ---------------------------------------------------------------------------
__global__ __launch_bounds__(NTHR, 2)
void lateral_kernel(const float* __restrict__ x, const float* __restrict__ Wl,
                    float* __restrict__ out_lat, float* __restrict__ out_xn,
                    float* __restrict__ out_bin) {
    __shared__ int   s_nnz;
    __shared__ float s_wsum;
    __shared__ float s_invmax;
    __shared__ short s_ti[CKK];
    __shared__ signed char s_dy[CKK];
    __shared__ signed char s_dx[CKK];
    __shared__ float s_tw[CKK];
    __shared__ float s_red[NTHR / 32];

    int slice = blockIdx.x;           // b*64 + o
    int b = slice >> 6, o = slice & 63;
    int tid  = threadIdx.x;
    int lane = tid & 31;

    // --- warp 0: compact nonzero weights of row o (ordered => deterministic)
    if (tid < 32) {
        const float* row = Wl + (long)o * CKK;
        int cnt = 0;
        float ws = 0.f;
        for (int base = 0; base < CKK; base += 32) {     // 1600 % 32 == 0
            int j = base + lane;
            float w = row[j];
            ws += w;
            unsigned m = __ballot_sync(0xffffffffu, w != 0.f);
            int pos = cnt + __popc(m & ((1u << lane) - 1u));
            if (w != 0.f) {
                int i = j / 25, r = j % 25;
                s_ti[pos] = (short)i;
                s_dy[pos] = (signed char)(r / 5 - 2);
                s_dx[pos] = (signed char)(r % 5 - 2);
                s_tw[pos] = w;
            }
            cnt += __popc(m);
        }
#pragma unroll
        for (int off = 16; off; off >>= 1)
            ws += __shfl_xor_sync(0xffffffffu, ws, off);
        if (lane == 0) { s_nnz = cnt; s_wsum = ws; }
    }
    __syncthreads();

    const int   nnz    = s_nnz;
    const float inv_ws = 1.f / (1e-10f + s_wsum);
    const float* xb = x + ((long)b * CC * HWSZ);
    const float* invm_b = g_invm + (b << 14);
    const long base_out = (long)slice * HWSZ;

    // ============ pass 1: conv (register-cached) + per-slice max ============
    float4 racc[NV];
    float lmax = -3.402823466e38f;
#pragma unroll
    for (int it = 0; it < NV; it++) {
        int v = tid + it * NTHR;            // < 4096
        int p = v << 2;
        int h = p >> 7, w = p & (WW - 1);
        float4 acc = make_float4(0.f, 0.f, 0.f, 0.f);
        bool interior = (h >= 2) & (h < HH - 2) & (w >= 2) & (w + 3 < WW - 2);
        if (interior) {
            for (int t = 0; t < nnz; t++) {
                const float* src = xb + ((int)s_ti[t] << 14)
                                 + ((h + (int)s_dy[t]) << 7) + (w + (int)s_dx[t]);
                float tw = s_tw[t];
                acc.x += tw * src[0]; acc.y += tw * src[1];
                acc.z += tw * src[2]; acc.w += tw * src[3];
            }
        } else {
            for (int t = 0; t < nnz; t++) {
                int hy = h + (int)s_dy[t];
                if ((unsigned)hy >= (unsigned)HH) continue;
                const float* src = xb + ((int)s_ti[t] << 14) + (hy << 7);
                float tw = s_tw[t];
                int wx = w + (int)s_dx[t];
#pragma unroll
                for (int q = 0; q < 4; q++) {
                    int w2 = wx + q;
                    if ((unsigned)w2 < (unsigned)WW)
                        (&acc.x)[q] += tw * src[w2];
                }
            }
        }
        racc[it] = acc;
        // pre = acc * invm * inv_ws (inv_ws applied per-element: sign-safe)
        float4 im = ((const float4*)invm_b)[v];
        lmax = fmaxf(lmax,
               fmaxf(fmaxf(acc.x * im.x * inv_ws, acc.y * im.y * inv_ws),
                     fmaxf(acc.z * im.z * inv_ws, acc.w * im.w * inv_ws)));
    }

    // --- deterministic block max reduce ---
#pragma unroll
    for (int off = 16; off; off >>= 1)
        lmax = fmaxf(lmax, __shfl_xor_sync(0xffffffffu, lmax, off));
    if (lane == 0) s_red[tid >> 5] = lmax;
    __syncthreads();
    if (tid < 32) {
        const int nw = NTHR / 32;           // 16 warps
        float v = (tid < nw) ? s_red[tid] : -3.402823466e38f;
#pragma unroll
        for (int off = 16; off; off >>= 1)
            v = fmaxf(v, __shfl_xor_sync(0xffffffffu, v, off));
        if (tid == 0) s_invmax = 1.f / (1e-10f + v);
    }
    __syncthreads();
    const float inv_max = s_invmax;
    const float kscale  = inv_ws * inv_max;

    // ========= pass 2: streaming stores only (conv cached in regs) =========
#pragma unroll
    for (int it = 0; it < NV; it++) {
        int v = tid + it * NTHR;
        float4 acc = racc[it];
        __stcs((float4*)(out_lat + base_out) + v, acc);

        float4 im = ((const float4*)invm_b)[v];
        float4 xn;
        xn.x = acc.x * im.x * kscale;
        xn.y = acc.y * im.y * kscale;
        xn.z = acc.z * im.z * kscale;
        xn.w = acc.w * im.w * kscale;
        __stcs((float4*)(out_xn + base_out) + v, xn);

        float4 bin;
        bin.x = (xn.x * xn.x * xn.x >= 0.5f) ? 1.f : 0.f;
        bin.y = (xn.y * xn.y * xn.y >= 0.5f) ? 1.f : 0.f;
        bin.z = (xn.z * xn.z * xn.z >= 0.5f) ? 1.f : 0.f;
        bin.w = (xn.w * xn.w * xn.w >= 0.5f) ? 1.f : 0.f;
        __stcs((float4*)(out_bin + base_out) + v, bin);
    }
}

// ---------------------------------------------------------------------------
extern "C" void kernel_launch(void* const* d_in, const int* in_sizes, int n_in,
                              void* d_out, int out_size) {
    const float* x  = (const float*)d_in[0];
    const float* Wl = (const float*)d_in[1];
    // Defensive: identify by element count (x: 4194304, W: 102400)
    if (n_in >= 2 && in_sizes[0] == CC * CKK && in_sizes[1] == NEL) {
        const float* t = x; x = Wl; Wl = t;
    }
    float* out      = (float*)d_out;
    float* out_lat  = out;
    float* out_xn   = out + (long)NEL;
    float* out_bin  = out + 2L * NEL;

    chansum_kernel<<<128, 128>>>(x);                     // 16384 vectors
    box_kernel<<<(BB * HWSZ + 255) / 256, 256>>>();
    lateral_kernel<<<NSL, NTHR>>>(x, Wl, out_lat, out_xn, out_bin);
}

// round 10
// speedup vs baseline: 1.2206x; 1.2206x over previous
#include <cuda_runtime.h>
#include <cuda_bf16.h>

// LateralLayer: B=4, C_IN=C_OUT=64, H=W=128, K=5 (LOC=2)
// d_out (float32): [0:N) x_lateral | [N:2N) xn | [2N:3N) x_lateral_bin
// N = 4*64*128*128 = 4194304.

#define BB   4
#define CC   64
#define HH   128
#define WW   128
#define KK   5
#define CKK  (CC * KK * KK)   // 1600
#define HWSZ (HH * WW)        // 16384
#define NSL  (BB * CC)        // 256
#define NEL  (NSL * HWSZ)     // 4194304
#define NTHR 512
#define NV   (HWSZ / 4 / NTHR)   // 8 float4 vectors per thread

// Scratch (device globals; allocation is forbidden)
__device__ float g_s[BB * HWSZ];      // channel-sum per pixel
__device__ float g_invm[BB * HWSZ];   // 1 / max(boxsum, K)

// ---------------------------------------------------------------------------
// Kernel 1: channel sum. 512 blocks x 256 thr; block owns 32 float4 vectors,
// each of 8 warps sums 8 channels (coalesced 512B per load instruction),
// partials combined via smem in a fixed order (deterministic).
// ---------------------------------------------------------------------------
__global__ void chansum_kernel(const float* __restrict__ x) {
    __shared__ float4 s_p[8][32];
    int warp = threadIdx.x >> 5, lane = threadIdx.x & 31;
    int v = (blockIdx.x << 5) + lane;          // vector index < 16384
    int p = v << 2;
    int b = p >> 14;
    int hw = p & (HWSZ - 1);
    const float4* xb = (const float4*)(x + ((long)b * CC * HWSZ));
    int vo = hw >> 2;
    float4 s = make_float4(0.f, 0.f, 0.f, 0.f);
#pragma unroll
    for (int i = 0; i < 8; i++) {
        int c = (warp << 3) + i;
        float4 t = __ldg(&xb[(c << 12) + vo]);
        s.x += t.x; s.y += t.y; s.z += t.z; s.w += t.w;
    }
    s_p[warp][lane] = s;
    __syncthreads();
    if (warp == 0) {
        float4 acc = s_p[0][lane];
#pragma unroll
        for (int q = 1; q < 8; q++) {
            float4 t = s_p[q][lane];
            acc.x += t.x; acc.y += t.y; acc.z += t.z; acc.w += t.w;
        }
        ((float4*)g_s)[v] = acc;
    }
}

// ---------------------------------------------------------------------------
// Kernel 2: 5x5 box sum (zero pad) of g_s, invm = 1/max(sum, 5)  (256KB total)
// ---------------------------------------------------------------------------
__global__ void box_kernel() {
    int p = blockIdx.x * blockDim.x + threadIdx.x;
    if (p >= BB * HWSZ) return;
    int b  = p >> 14;
    int hw = p & (HWSZ - 1);
    int h = hw >> 7, w = hw & (WW - 1);
    const float* __restrict__ sb = g_s + (b << 14);
    float acc = 0.f;
#pragma unroll
    for (int dy = -2; dy <= 2; dy++) {
        int hy = h + dy;
        if ((unsigned)hy >= (unsigned)HH) continue;
#pragma unroll
        for (int dx = -2; dx <= 2; dx++) {
            int wx = w + dx;
            if ((unsigned)wx >= (unsigned)WW) continue;
            acc += sb[(hy << 7) + wx];
        }
    }
    g_invm[p] = 1.f / fmaxf(acc, (float)KK);
}

// ---------------------------------------------------------------------------
// Kernel 3 (fused): sparse lateral conv + normalization + max + binarize.
// One block per (b,o) slice; 512 thr x occupancy 2 -> single wave.
// Fast path for nnz==1 && dx==0 (identity init): one aligned float4 load per
// vector. General ballot-compacted tap loop retained for arbitrary W.
// ---------------------------------------------------------------------------
__global__ __launch_bounds__(NTHR, 2)
void lateral_kernel(const float* __restrict__ x, const float* __restrict__ Wl,
                    float* __restrict__ out_lat, float* __restrict__ out_xn,
                    float* __restrict__ out_bin) {
    __shared__ int   s_nnz;
    __shared__ float s_wsum;
    __shared__ float s_invmax;
    __shared__ short s_ti[CKK];
    __shared__ signed char s_dy[CKK];
    __shared__ signed char s_dx[CKK];
    __shared__ float s_tw[CKK];
    __shared__ float s_red[NTHR / 32];

    int slice = blockIdx.x;           // b*64 + o
    int b = slice >> 6, o = slice & 63;
    int tid  = threadIdx.x;
    int lane = tid & 31;

    // --- warp 0: compact nonzero weights of row o (ordered => deterministic)
    if (tid < 32) {
        const float* row = Wl + (long)o * CKK;
        int cnt = 0;
        float ws = 0.f;
        for (int base = 0; base < CKK; base += 32) {     // 1600 % 32 == 0
            int j = base + lane;
            float w = row[j];
            ws += w;
            unsigned m = __ballot_sync(0xffffffffu, w != 0.f);
            int pos = cnt + __popc(m & ((1u << lane) - 1u));
            if (w != 0.f) {
                int i = j / 25, r = j % 25;
                s_ti[pos] = (short)i;
                s_dy[pos] = (signed char)(r / 5 - 2);
                s_dx[pos] = (signed char)(r % 5 - 2);
                s_tw[pos] = w;
            }
            cnt += __popc(m);
        }
#pragma unroll
        for (int off = 16; off; off >>= 1)
            ws += __shfl_xor_sync(0xffffffffu, ws, off);
        if (lane == 0) { s_nnz = cnt; s_wsum = ws; }
    }
    __syncthreads();

    const int   nnz    = s_nnz;
    const float inv_ws = 1.f / (1e-10f + s_wsum);
    const float* xb = x + ((long)b * CC * HWSZ);
    const float* invm_b = g_invm + (b << 14);
    const long base_out = (long)slice * HWSZ;

    const bool fast1 = (nnz == 1) && (s_dx[0] == 0);
    const int  f_dy  = fast1 ? (int)s_dy[0] : 0;
    const float f_tw = fast1 ? s_tw[0] : 0.f;
    const float4* f_src = fast1
        ? (const float4*)(xb + ((int)s_ti[0] << 14)) : (const float4*)xb;

    // ============ pass 1: conv (register-cached) + per-slice max ============
    float4 racc[NV];
    float lmax = -3.402823466e38f;
#pragma unroll
    for (int it = 0; it < NV; it++) {
        int v = tid + it * NTHR;            // < 4096
        int p = v << 2;
        int h = p >> 7, w = p & (WW - 1);
        float4 acc = make_float4(0.f, 0.f, 0.f, 0.f);
        if (fast1) {
            int hy = h + f_dy;
            if ((unsigned)hy < (unsigned)HH) {
                float4 t = f_src[(hy << 5) + (v & 31)];  // aligned: dx==0
                acc.x = f_tw * t.x; acc.y = f_tw * t.y;
                acc.z = f_tw * t.z; acc.w = f_tw * t.w;
            }
        } else {
            bool interior = (h >= 2) & (h < HH - 2) & (w >= 2) & (w + 3 < WW - 2);
            if (interior) {
                for (int t = 0; t < nnz; t++) {
                    const float* src = xb + ((int)s_ti[t] << 14)
                                     + ((h + (int)s_dy[t]) << 7) + (w + (int)s_dx[t]);
                    float tw = s_tw[t];
                    acc.x += tw * src[0]; acc.y += tw * src[1];
                    acc.z += tw * src[2]; acc.w += tw * src[3];
                }
            } else {
                for (int t = 0; t < nnz; t++) {
                    int hy = h + (int)s_dy[t];
                    if ((unsigned)hy >= (unsigned)HH) continue;
                    const float* src = xb + ((int)s_ti[t] << 14) + (hy << 7);
                    float tw = s_tw[t];
                    int wx = w + (int)s_dx[t];
#pragma unroll
                    for (int q = 0; q < 4; q++) {
                        int w2 = wx + q;
                        if ((unsigned)w2 < (unsigned)WW)
                            (&acc.x)[q] += tw * src[w2];
                    }
                }
            }
        }
        racc[it] = acc;
        // pre = acc * invm * inv_ws (inv_ws applied per-element: sign-safe)
        float4 im = ((const float4*)invm_b)[v];
        lmax = fmaxf(lmax,
               fmaxf(fmaxf(acc.x * im.x * inv_ws, acc.y * im.y * inv_ws),
                     fmaxf(acc.z * im.z * inv_ws, acc.w * im.w * inv_ws)));
    }

    // --- deterministic block max reduce ---
#pragma unroll
    for (int off = 16; off; off >>= 1)
        lmax = fmaxf(lmax, __shfl_xor_sync(0xffffffffu, lmax, off));
    if (lane == 0) s_red[tid >> 5] = lmax;
    __syncthreads();
    if (tid < 32) {
        const int nw = NTHR / 32;           // 16 warps
        float v = (tid < nw) ? s_red[tid] : -3.402823466e38f;
#pragma unroll
        for (int off = 16; off; off >>= 1)
            v = fmaxf(v, __shfl_xor_sync(0xffffffffu, v, off));
        if (tid == 0) s_invmax = 1.f / (1e-10f + v);
    }
    __syncthreads();
    const float inv_max = s_invmax;
    const float kscale  = inv_ws * inv_max;

    // ========= pass 2: streaming stores only (conv cached in regs) =========
#pragma unroll
    for (int it = 0; it < NV; it++) {
        int v = tid + it * NTHR;
        float4 acc = racc[it];
        __stcs((float4*)(out_lat + base_out) + v, acc);

        float4 im = ((const float4*)invm_b)[v];   // L1-hit (read in pass 1)
        float4 xn;
        xn.x = acc.x * im.x * kscale;
        xn.y = acc.y * im.y * kscale;
        xn.z = acc.z * im.z * kscale;
        xn.w = acc.w * im.w * kscale;
        __stcs((float4*)(out_xn + base_out) + v, xn);

        float4 bin;
        bin.x = (xn.x * xn.x * xn.x >= 0.5f) ? 1.f : 0.f;
        bin.y = (xn.y * xn.y * xn.y >= 0.5f) ? 1.f : 0.f;
        bin.z = (xn.z * xn.z * xn.z >= 0.5f) ? 1.f : 0.f;
        bin.w = (xn.w * xn.w * xn.w >= 0.5f) ? 1.f : 0.f;
        __stcs((float4*)(out_bin + base_out) + v, bin);
    }
}

// ---------------------------------------------------------------------------
extern "C" void kernel_launch(void* const* d_in, const int* in_sizes, int n_in,
                              void* d_out, int out_size) {
    const float* x  = (const float*)d_in[0];
    const float* Wl = (const float*)d_in[1];
    // Defensive: identify by element count (x: 4194304, W: 102400)
    if (n_in >= 2 && in_sizes[0] == CC * CKK && in_sizes[1] == NEL) {
        const float* t = x; x = Wl; Wl = t;
    }
    float* out      = (float*)d_out;
    float* out_lat  = out;
    float* out_xn   = out + (long)NEL;
    float* out_bin  = out + 2L * NEL;

    chansum_kernel<<<512, 256>>>(x);          // 32 vectors per block
    box_kernel<<<BB * HWSZ / 256, 256>>>();
    lateral_kernel<<<NSL, NTHR>>>(x, Wl, out_lat, out_xn, out_bin);
}

// round 16
// speedup vs baseline: 1.6772x; 1.3741x over previous
#include <cuda_runtime.h>
#include <cuda_bf16.h>

// LateralLayer: B=4, C_IN=C_OUT=64, H=W=128, K=5 (LOC=2)
// d_out (float32): [0:N) x_lateral | [N:2N) xn | [2N:3N) x_lateral_bin

#define BB   4
#define CC   64
#define HH   128
#define WW   128
#define KK   5
#define CKK  (CC * KK * KK)   // 1600
#define HWSZ (HH * WW)        // 16384
#define NSL  (BB * CC)        // 256
#define NEL  (NSL * HWSZ)     // 4194304
#define NTHR 512
#define NV   (HWSZ / 4 / NTHR)   // 8 float4 vectors per thread
#define CHUNK 100                // CKK / 16 warps

// Scratch (device globals; allocation is forbidden)
__device__ float g_s[BB * HWSZ];      // channel-sum per pixel
__device__ float g_invm[BB * HWSZ];   // 1 / max(boxsum, K)

// ---------------------------------------------------------------------------
// Kernel 1: channel sum. 512 blocks x 512 thr; block owns 32 float4 vectors,
// each of 16 warps sums 4 channels (coalesced 512B per load instruction),
// partials combined via smem in a fixed order (deterministic).
// ---------------------------------------------------------------------------
__global__ void chansum_kernel(const float* __restrict__ x) {
    __shared__ float4 s_p[16][32];
    int warp = threadIdx.x >> 5, lane = threadIdx.x & 31;
    int v = (blockIdx.x << 5) + lane;          // vector index < 16384
    int p = v << 2;
    int b = p >> 14;
    int hw = p & (HWSZ - 1);
    const float4* xb = (const float4*)(x + ((long)b * CC * HWSZ));
    int vo = hw >> 2;
    float4 s = make_float4(0.f, 0.f, 0.f, 0.f);
#pragma unroll
    for (int i = 0; i < 4; i++) {
        int c = (warp << 2) + i;
        float4 t = __ldg(&xb[(c << 12) + vo]);
        s.x += t.x; s.y += t.y; s.z += t.z; s.w += t.w;
    }
    s_p[warp][lane] = s;
    __syncthreads();
    if (warp == 0) {
        float4 acc = s_p[0][lane];
#pragma unroll
        for (int q = 1; q < 16; q++) {
            float4 t = s_p[q][lane];
            acc.x += t.x; acc.y += t.y; acc.z += t.z; acc.w += t.w;
        }
        ((float4*)g_s)[v] = acc;
    }
}

// ---------------------------------------------------------------------------
// Kernel 2: 5x5 box sum (zero pad) of g_s, invm = 1/max(sum, 5)  (256KB total)
// ---------------------------------------------------------------------------
__global__ void box_kernel() {
    int p = blockIdx.x * blockDim.x + threadIdx.x;
    if (p >= BB * HWSZ) return;
    int b  = p >> 14;
    int hw = p & (HWSZ - 1);
    int h = hw >> 7, w = hw & (WW - 1);
    const float* __restrict__ sb = g_s + (b << 14);
    float acc = 0.f;
#pragma unroll
    for (int dy = -2; dy <= 2; dy++) {
        int hy = h + dy;
        if ((unsigned)hy >= (unsigned)HH) continue;
#pragma unroll
        for (int dx = -2; dx <= 2; dx++) {
            int wx = w + dx;
            if ((unsigned)wx >= (unsigned)WW) continue;
            acc += sb[(hy << 7) + wx];
        }
    }
    g_invm[p] = 1.f / fmaxf(acc, (float)KK);
}

// ---------------------------------------------------------------------------
// Kernel 3 (fused): sparse lateral conv + normalization + max + binarize.
// One block per (b,o) slice; 512 thr x occupancy 2 -> single wave.
// Weight-row compaction parallelized across ALL 16 warps (count -> scan ->
// write, preserving j-order => deterministic for any W). Fast path for
// nnz==1 && dx==0 (identity init): one aligned float4 load per vector.
// ---------------------------------------------------------------------------
__global__ __launch_bounds__(NTHR, 2)
void lateral_kernel(const float* __restrict__ x, const float* __restrict__ Wl,
                    float* __restrict__ out_lat, float* __restrict__ out_xn,
                    float* __restrict__ out_bin) {
    __shared__ int   s_nnz;
    __shared__ float s_wsum;
    __shared__ float s_invmax;
    __shared__ short s_ti[CKK];
    __shared__ signed char s_dy[CKK];
    __shared__ signed char s_dx[CKK];
    __shared__ float s_tw[CKK];
    __shared__ float s_red[NTHR / 32];
    __shared__ int   s_wcnt[16];
    __shared__ float s_wws[16];
    __shared__ int   s_woff[16];

    int slice = blockIdx.x;           // b*64 + o
    int b = slice >> 6, o = slice & 63;
    int tid  = threadIdx.x;
    int lane = tid & 31;
    int warp = tid >> 5;              // 0..15

    const float* row = Wl + (long)o * CKK;
    const int begin = warp * CHUNK, end = begin + CHUNK;

    // --- phase A: per-warp count + weight-sum over its 100-entry chunk ---
    {
        int cnt = 0; float ws = 0.f;
        for (int base = begin; base < end; base += 32) {
            int j = base + lane;
            bool in = (j < end);
            float w = in ? row[j] : 0.f;
            ws += w;
            unsigned m = __ballot_sync(0xffffffffu, in && (w != 0.f));
            cnt += __popc(m);
        }
#pragma unroll
        for (int off = 16; off; off >>= 1)
            ws += __shfl_xor_sync(0xffffffffu, ws, off);
        if (lane == 0) { s_wcnt[warp] = cnt; s_wws[warp] = ws; }
    }
    __syncthreads();

    // --- warp 0: exclusive scan of 16 counts; totals ---
    if (tid < 32) {
        int c = (lane < 16) ? s_wcnt[lane] : 0;
        float ws = (lane < 16) ? s_wws[lane] : 0.f;
        int sc = c;
#pragma unroll
        for (int off = 1; off < 16; off <<= 1) {
            int t = __shfl_up_sync(0xffffffffu, sc, off);
            if (lane >= off) sc += t;
        }
        if (lane < 16) s_woff[lane] = sc - c;
        if (lane == 15) s_nnz = sc;
#pragma unroll
        for (int off = 16; off; off >>= 1)
            ws += __shfl_xor_sync(0xffffffffu, ws, off);
        if (lane == 0) s_wsum = ws;
    }
    __syncthreads();

    // --- phase B: each warp writes its compacted entries (j-order kept) ---
    {
        int off = s_woff[warp];
        for (int base = begin; base < end; base += 32) {
            int j = base + lane;
            bool in = (j < end);
            float w = in ? row[j] : 0.f;      // L1-hit (phase A read it)
            unsigned m = __ballot_sync(0xffffffffu, in && (w != 0.f));
            int pos = off + __popc(m & ((1u << lane) - 1u));
            if (in && w != 0.f) {
                int i = j / 25, r = j % 25;
                s_ti[pos] = (short)i;
                s_dy[pos] = (signed char)(r / 5 - 2);
                s_dx[pos] = (signed char)(r % 5 - 2);
                s_tw[pos] = w;
            }
            off += __popc(m);
        }
    }
    __syncthreads();

    const int   nnz    = s_nnz;
    const float inv_ws = 1.f / (1e-10f + s_wsum);
    const float* xb = x + ((long)b * CC * HWSZ);
    const float* invm_b = g_invm + (b << 14);
    const long base_out = (long)slice * HWSZ;

    const bool fast1 = (nnz == 1) && (s_dx[0] == 0);
    const int  f_dy  = fast1 ? (int)s_dy[0] : 0;
    const float f_tw = fast1 ? s_tw[0] : 0.f;
    const float4* f_src = fast1
        ? (const float4*)(xb + ((int)s_ti[0] << 14)) : (const float4*)xb;

    // ============ pass 1: conv (register-cached) + per-slice max ============
    float4 racc[NV];
    float lmax = -3.402823466e38f;
#pragma unroll
    for (int it = 0; it < NV; it++) {
        int v = tid + it * NTHR;            // < 4096
        int p = v << 2;
        int h = p >> 7, w = p & (WW - 1);
        float4 acc = make_float4(0.f, 0.f, 0.f, 0.f);
        if (fast1) {
            int hy = h + f_dy;
            if ((unsigned)hy < (unsigned)HH) {
                float4 t = f_src[(hy << 5) + (v & 31)];  // aligned: dx==0
                acc.x = f_tw * t.x; acc.y = f_tw * t.y;
                acc.z = f_tw * t.z; acc.w = f_tw * t.w;
            }
        } else {
            bool interior = (h >= 2) & (h < HH - 2) & (w >= 2) & (w + 3 < WW - 2);
            if (interior) {
                for (int t = 0; t < nnz; t++) {
                    const float* src = xb + ((int)s_ti[t] << 14)
                                     + ((h + (int)s_dy[t]) << 7) + (w + (int)s_dx[t]);
                    float tw = s_tw[t];
                    acc.x += tw * src[0]; acc.y += tw * src[1];
                    acc.z += tw * src[2]; acc.w += tw * src[3];
                }
            } else {
                for (int t = 0; t < nnz; t++) {
                    int hy = h + (int)s_dy[t];
                    if ((unsigned)hy >= (unsigned)HH) continue;
                    const float* src = xb + ((int)s_ti[t] << 14) + (hy << 7);
                    float tw = s_tw[t];
                    int wx = w + (int)s_dx[t];
#pragma unroll
                    for (int q = 0; q < 4; q++) {
                        int w2 = wx + q;
                        if ((unsigned)w2 < (unsigned)WW)
                            (&acc.x)[q] += tw * src[w2];
                    }
                }
            }
        }
        racc[it] = acc;
        float4 im = ((const float4*)invm_b)[v];
        lmax = fmaxf(lmax,
               fmaxf(fmaxf(acc.x * im.x * inv_ws, acc.y * im.y * inv_ws),
                     fmaxf(acc.z * im.z * inv_ws, acc.w * im.w * inv_ws)));
    }

    // --- deterministic block max reduce ---
#pragma unroll
    for (int off = 16; off; off >>= 1)
        lmax = fmaxf(lmax, __shfl_xor_sync(0xffffffffu, lmax, off));
    if (lane == 0) s_red[warp] = lmax;
    __syncthreads();
    if (tid < 32) {
        const int nw = NTHR / 32;           // 16 warps
        float v = (tid < nw) ? s_red[tid] : -3.402823466e38f;
#pragma unroll
        for (int off = 16; off; off >>= 1)
            v = fmaxf(v, __shfl_xor_sync(0xffffffffu, v, off));
        if (tid == 0) s_invmax = 1.f / (1e-10f + v);
    }
    __syncthreads();
    const float inv_max = s_invmax;
    const float kscale  = inv_ws * inv_max;

    // ========= pass 2: streaming stores only (conv cached in regs) =========
#pragma unroll
    for (int it = 0; it < NV; it++) {
        int v = tid + it * NTHR;
        float4 acc = racc[it];
        __stcs((float4*)(out_lat + base_out) + v, acc);

        float4 im = ((const float4*)invm_b)[v];   // L1-hit (read in pass 1)
        float4 xn;
        xn.x = acc.x * im.x * kscale;
        xn.y = acc.y * im.y * kscale;
        xn.z = acc.z * im.z * kscale;
        xn.w = acc.w * im.w * kscale;
        __stcs((float4*)(out_xn + base_out) + v, xn);

        float4 bin;
        bin.x = (xn.x * xn.x * xn.x >= 0.5f) ? 1.f : 0.f;
        bin.y = (xn.y * xn.y * xn.y >= 0.5f) ? 1.f : 0.f;
        bin.z = (xn.z * xn.z * xn.z >= 0.5f) ? 1.f : 0.f;
        bin.w = (xn.w * xn.w * xn.w >= 0.5f) ? 1.f : 0.f;
        __stcs((float4*)(out_bin + base_out) + v, bin);
    }
}

// ---------------------------------------------------------------------------
extern "C" void kernel_launch(void* const* d_in, const int* in_sizes, int n_in,
                              void* d_out, int out_size) {
    const float* x  = (const float*)d_in[0];
    const float* Wl = (const float*)d_in[1];
    // Defensive: identify by element count (x: 4194304, W: 102400)
    if (n_in >= 2 && in_sizes[0] == CC * CKK && in_sizes[1] == NEL) {
        const float* t = x; x = Wl; Wl = t;
    }
    float* out      = (float*)d_out;
    float* out_lat  = out;
    float* out_xn   = out + (long)NEL;
    float* out_bin  = out + 2L * NEL;

    chansum_kernel<<<512, 512>>>(x);          // 32 vectors, 16 warps per block
    box_kernel<<<BB * HWSZ / 256, 256>>>();
    lateral_kernel<<<NSL, NTHR>>>(x, Wl, out_lat, out_xn, out_bin);
}